// round 6
// baseline (speedup 1.0000x reference)
#include <cuda_runtime.h>
#include <math.h>

#define DD 256   // feature dim D
#define SS 8     // memory slots S
#define MAXB 512
#define MAXT 256
#define TM 32    // rows per XW tile

typedef unsigned long long u64;

// ---- packed fp32x2 helpers (Blackwell; IEEE-identical to scalar fp32) ----
__device__ __forceinline__ u64 pack2(float lo, float hi) {
    u64 r; asm("mov.b64 %0, {%1, %2};" : "=l"(r) : "f"(lo), "f"(hi)); return r;
}
__device__ __forceinline__ void fma2(u64& acc, u64 a, u64 b) {
    asm("fma.rn.f32x2 %0, %1, %2, %0;" : "+l"(acc) : "l"(a), "l"(b));
}
__device__ __forceinline__ u64 add2(u64 a, u64 b) {
    u64 r; asm("add.rn.f32x2 %0, %1, %2;" : "=l"(r) : "l"(a), "l"(b)); return r;
}
__device__ __forceinline__ float2 unpack2(u64 v) {
    float lo, hi; asm("mov.b64 {%0, %1}, %2;" : "=f"(lo), "=f"(hi) : "l"(v));
    return make_float2(lo, hi);
}

// Legal scratch: __device__ globals.
__device__ float g_xw[(size_t)MAXB * MAXT * DD];         // x@W     [B,T,D]
__device__ float g_gk[(size_t)MAXB * MAXT * SS];         // x@keys^T[B,T,S]

// ---------------------------------------------------------------------------
// Precompute XW[b,t,:] = x@W and GK[b,t,:] = x@keys^T for t < len[b].
// ---------------------------------------------------------------------------
__global__ __launch_bounds__(256) void xw_kernel(
    const float* __restrict__ inputs,   // [B,T,D]
    const int*   __restrict__ lengths,
    const float* __restrict__ W,        // [D,D]
    const float* __restrict__ keys,     // [S,D]
    int T)
{
    const int b  = blockIdx.y;
    const int t0 = blockIdx.x * TM;
    if (t0 >= lengths[b]) return;        // fully-masked tile: no work
    const int rows = min(TM, T - t0);

    __shared__ __align__(16) float As[DD][TM];   // transposed x-tile, 32KB
    const float* A = inputs + ((size_t)b * T + t0) * DD;
    const int tid = threadIdx.x;

    for (int i = tid; i < rows * (DD / 4); i += 256) {
        const int m = i / (DD / 4), d4 = i % (DD / 4);
        const float4 v = *(const float4*)&A[(size_t)m * DD + d4 * 4];
        As[d4 * 4 + 0][m] = v.x;
        As[d4 * 4 + 1][m] = v.y;
        As[d4 * 4 + 2][m] = v.z;
        As[d4 * 4 + 3][m] = v.w;
    }
    __syncthreads();

    const int e = tid;
    u64 acc2[TM / 2];
#pragma unroll
    for (int m = 0; m < TM / 2; ++m) acc2[m] = 0ull;
    const float* wp = W + e;
#pragma unroll 2
    for (int d = 0; d < DD; ++d) {
        const float w = *wp; wp += DD;
        const u64 ww = pack2(w, w);
        const ulonglong2* ap = (const ulonglong2*)&As[d][0];
#pragma unroll
        for (int m4 = 0; m4 < TM / 4; ++m4) {
            const ulonglong2 a = ap[m4];
            fma2(acc2[m4 * 2 + 0], a.x, ww);
            fma2(acc2[m4 * 2 + 1], a.y, ww);
        }
    }
    float* o = g_xw + ((size_t)b * T + t0) * DD + e;
    for (int m = 0; m < rows; ++m) {
        const float2 f = unpack2(acc2[m >> 1]);
        o[(size_t)m * DD] = (m & 1) ? f.y : f.x;
    }

    // GK tail: 32 rows x 8 slots = 256 dot products, one per thread.
    {
        const int m = tid >> 3, s = tid & 7;
        if (m < rows) {
            const float* kp = keys + s * DD;
            float v = 0.f;
#pragma unroll 4
            for (int d = 0; d < DD; ++d) v = fmaf(As[d][m], kp[d], v);
            g_gk[((size_t)b * T + t0 + m) * SS + s] = v;
        }
    }
}

// ---------------------------------------------------------------------------
// Recurrence: one CTA of 512 threads per BATCH PAIR (2b, 2b+1), running
// max(lenA, lenB) steps with per-batch masked updates. Thread = (column e,
// half). GEMM d-split: half h covers d in [128h, 128h+128) (disjoint U rows,
// loaded once and shared by BOTH batches -> 8 FMA2 per LDG). Cross-half merge
// via one 32B SMEM exchange under S1. Phase B: half h finalizes batch h.
// Raw state + deferred per-slot norm scale r[] as before; 2 barriers/step.
// ---------------------------------------------------------------------------
__global__ __launch_bounds__(512, 1) void dm_kernel(
    const float* __restrict__ inputs,
    const int*   __restrict__ lengths,
    const float* __restrict__ keys,
    const float* __restrict__ U,
    const float* __restrict__ V,
    const float* __restrict__ gate_bias,
    const float* __restrict__ state_bias,
    float*       __restrict__ out,
    int T, int B)
{
    const int tid  = threadIdx.x;
    const int e    = tid & (DD - 1);
    const int half = tid >> 8;          // d-half in GEMM; owned batch in B
    const int lane = tid & 31;
    const int wh   = (tid >> 5) & 7;    // warp index within half

    const int bA = blockIdx.x * 2;
    const int bBr = bA + 1;
    const int bB = (bBr < B) ? bBr : bA;    // clamp for odd B (B=512: unused)

    __shared__ __align__(16) float stA[DD][SS];   // raw h, batch A, [d][s]
    __shared__ __align__(16) float stB[DD][SS];   // raw h, batch B
    __shared__ __align__(16) u64   part[2][DD][4];// cross-half GEMM exchange
    __shared__ __align__(16) float red1[2][SS][8];// gate partials [batch][s][w]
    __shared__ __align__(16) float red2[2][SS][8];// norm partials

#pragma unroll
    for (int s = 0; s < SS; ++s) {
        const float k = keys[s * DD + e];
        if (half == 0) stA[e][s] = k; else stB[e][s] = k;  // init = keys, r=1
    }
    __syncthreads();

    // ---- kvb[e][s] = sum_d keys[s][d]*V[d][e] + sbias[e] (registers) ----
    float kv[SS];
    {
        u64 K01 = 0ull, K23 = 0ull, K45 = 0ull, K67 = 0ull;
        const float* vp = V + e;
#pragma unroll 8
        for (int d = 0; d < DD; ++d) {
            const float v = *vp; vp += DD;
            const u64 vv = pack2(v, v);
            const ulonglong2 r0 = *(const ulonglong2*)&stA[d][0];  // == keys
            const ulonglong2 r1 = *(const ulonglong2*)&stA[d][4];
            fma2(K01, r0.x, vv);
            fma2(K23, r0.y, vv);
            fma2(K45, r1.x, vv);
            fma2(K67, r1.y, vv);
        }
        const float sb = state_bias[e];
        const float2 k01 = unpack2(K01), k23 = unpack2(K23);
        const float2 k45 = unpack2(K45), k67 = unpack2(K67);
        kv[0] = k01.x + sb; kv[1] = k01.y + sb;
        kv[2] = k23.x + sb; kv[3] = k23.y + sb;
        kv[4] = k45.x + sb; kv[5] = k45.y + sb;
        kv[6] = k67.x + sb; kv[7] = k67.y + sb;
    }

    const int lenA   = lengths[bA];
    const int lenB   = (bBr < B) ? lengths[bBr] : 0;
    const int len    = (lenA > lenB) ? lenA : lenB;
    const int bOwn   = half ? bB : bA;
    const int lenOwn = half ? lenB : lenA;
    const float gbias = gate_bias[0];

    const float* xb  = inputs + (size_t)bOwn * T * DD + e;
    const float* xwb = g_xw   + (size_t)bOwn * T * DD + e;
    const float* gkb = g_gk   + (size_t)bOwn * T * SS;
    const float* Up  = U + (size_t)(half * 128) * DD + e;

    float r[SS];
#pragma unroll
    for (int s = 0; s < SS; ++s) r[s] = 1.f;

    float  xv  = xb[0];
    float  xwv = xwb[0];
    float4 gk0 = *(const float4*)&gkb[0];
    float4 gk1 = *(const float4*)&gkb[4];

    for (int t = 0; t < len; ++t) {
        // ---- phase A: own-batch gate partials + d-split GEMM (both) ----
        float4 s0, s1;
        if (half == 0) { s0 = *(const float4*)&stA[e][0]; s1 = *(const float4*)&stA[e][4]; }
        else           { s0 = *(const float4*)&stB[e][0]; s1 = *(const float4*)&stB[e][4]; }
        float p[SS] = { xv * s0.x, xv * s0.y, xv * s0.z, xv * s0.w,
                        xv * s1.x, xv * s1.y, xv * s1.z, xv * s1.w };
#pragma unroll
        for (int s = 0; s < SS; ++s)
#pragma unroll
            for (int o = 16; o > 0; o >>= 1)
                p[s] += __shfl_xor_sync(0xffffffffu, p[s], o);
        if (lane == 0) {
#pragma unroll
            for (int s = 0; s < SS; ++s) red1[half][s][wh] = p[s];
        }

        // prefetch next step's own-batch scalars during the GEMM
        const int tcl = (lenOwn > 0) ? lenOwn - 1 : 0;
        const int tn  = (t + 1 < tcl) ? t + 1 : tcl;
        const float xv_n  = xb [(size_t)tn * DD];
        const float xw_n  = xwb[(size_t)tn * DD];
        const float4 gk0n = *(const float4*)&gkb[(size_t)tn * SS];
        const float4 gk1n = *(const float4*)&gkb[(size_t)tn * SS + 4];

        // GEMM over own 128-row d-range, BOTH batches share each U load
        u64 A01 = 0ull, A23 = 0ull, A45 = 0ull, A67 = 0ull;
        u64 B01 = 0ull, B23 = 0ull, B45 = 0ull, B67 = 0ull;
        {
            const float* up = Up;
            const int d0 = half * 128;
#pragma unroll 8
            for (int d = d0; d < d0 + 128; ++d) {
                const float u = *up; up += DD;
                const u64 uu = pack2(u, u);
                const ulonglong2 a0 = *(const ulonglong2*)&stA[d][0];
                const ulonglong2 a1 = *(const ulonglong2*)&stA[d][4];
                const ulonglong2 b0 = *(const ulonglong2*)&stB[d][0];
                const ulonglong2 b1 = *(const ulonglong2*)&stB[d][4];
                fma2(A01, a0.x, uu); fma2(A23, a0.y, uu);
                fma2(A45, a1.x, uu); fma2(A67, a1.y, uu);
                fma2(B01, b0.x, uu); fma2(B23, b0.y, uu);
                fma2(B45, b1.x, uu); fma2(B67, b1.y, uu);
            }
        }
        // ship the OTHER batch's partials to its owning half
        if (half == 0) {
            ulonglong2 v0 = {B01, B23}, v1 = {B45, B67};
            *(ulonglong2*)&part[1][e][0] = v0;
            *(ulonglong2*)&part[1][e][2] = v1;
        } else {
            ulonglong2 v0 = {A01, A23}, v1 = {A45, A67};
            *(ulonglong2*)&part[0][e][0] = v0;
            *(ulonglong2*)&part[0][e][2] = v1;
        }
        __syncthreads();   // S1: red1 + part visible; all st reads complete

        // ---- phase B: own batch only ----
        const ulonglong2 o0 = *(const ulonglong2*)&part[half][e][0];
        const ulonglong2 o1 = *(const ulonglong2*)&part[half][e][2];
        u64 P0, P1, P2, P3;
        if (half == 0) {
            P0 = add2(A01, o0.x); P1 = add2(A23, o0.y);
            P2 = add2(A45, o1.x); P3 = add2(A67, o1.y);
        } else {
            P0 = add2(B01, o0.x); P1 = add2(B23, o0.y);
            P2 = add2(B45, o1.x); P3 = add2(B67, o1.y);
        }
        const float2 f0 = unpack2(P0), f1 = unpack2(P1);
        const float2 f2 = unpack2(P2), f3 = unpack2(P3);
        const float acc[SS] = {f0.x, f0.y, f1.x, f1.y, f2.x, f2.y, f3.x, f3.y};
        const float gk [SS] = {gk0.x, gk0.y, gk0.z, gk0.w,
                               gk1.x, gk1.y, gk1.z, gk1.w};
        const float sv [SS] = {s0.x, s0.y, s0.z, s0.w, s1.x, s1.y, s1.z, s1.w};
        float h[SS], q[SS];
#pragma unroll
        for (int s = 0; s < SS; ++s) {
            const float4 u0 = *(const float4*)&red1[half][s][0];
            const float4 u1 = *(const float4*)&red1[half][s][4];
            const float ls = ((u0.x + u0.y) + (u0.z + u0.w))
                           + ((u1.x + u1.y) + (u1.z + u1.w));
            const float logit = fmaf(r[s], ls, gk[s] + gbias);
            const float g = __fdividef(1.f, 1.f + __expf(-logit));
            const float pre = fmaf(r[s], acc[s], kv[s] + xwv);
            const float ht  = pre > 0.f ? pre : (__expf(pre) - 1.f);
            h[s] = fmaf(r[s], sv[s], g * ht);
            q[s] = h[s] * h[s];
        }
        const bool act = (t < lenOwn);
        if (act) {
            if (half == 0) {
                *(float4*)&stA[e][0] = make_float4(h[0], h[1], h[2], h[3]);
                *(float4*)&stA[e][4] = make_float4(h[4], h[5], h[6], h[7]);
            } else {
                *(float4*)&stB[e][0] = make_float4(h[0], h[1], h[2], h[3]);
                *(float4*)&stB[e][4] = make_float4(h[4], h[5], h[6], h[7]);
            }
        }
#pragma unroll
        for (int s = 0; s < SS; ++s)
#pragma unroll
            for (int o = 16; o > 0; o >>= 1)
                q[s] += __shfl_xor_sync(0xffffffffu, q[s], o);
        if (lane == 0) {
#pragma unroll
            for (int s = 0; s < SS; ++s) red2[half][s][wh] = q[s];
        }
        __syncthreads();   // S2: red2 + st writes visible

        if (act) {
#pragma unroll
            for (int s = 0; s < SS; ++s) {
                const float4 u0 = *(const float4*)&red2[half][s][0];
                const float4 u1 = *(const float4*)&red2[half][s][4];
                const float n2 = ((u0.x + u0.y) + (u0.z + u0.w))
                               + ((u1.x + u1.y) + (u1.z + u1.w));
                r[s] = (n2 > 1e-24f) ? rsqrtf(n2) : 1e12f;
            }
        }
        xv = xv_n; xwv = xw_n; gk0 = gk0n; gk1 = gk1n;
    }

    if (half == 0 || bBr < B) {
        float* ob = out + (size_t)bOwn * SS * DD + e;
#pragma unroll
        for (int s = 0; s < SS; ++s)
            ob[s * DD] = (half ? stB[e][s] : stA[e][s]) * r[s];
    }
}

// ---------------------------------------------------------------------------
// Inputs: inputs, lengths, keys, U, V, W, gate_bias, state_bias. Out: [B,S,D].
// ---------------------------------------------------------------------------
extern "C" void kernel_launch(void* const* d_in, const int* in_sizes, int n_in,
                              void* d_out, int out_size) {
    const float* inputs     = (const float*)d_in[0];
    const int*   lengths    = (const int*)  d_in[1];
    const float* keys       = (const float*)d_in[2];
    const float* U          = (const float*)d_in[3];
    const float* V          = (const float*)d_in[4];
    const float* W          = (const float*)d_in[5];
    const float* gate_bias  = (const float*)d_in[6];
    const float* state_bias = (const float*)d_in[7];

    const int B = in_sizes[1];                 // lengths element count
    const int T = in_sizes[0] / (B * DD);      // inputs = B*T*D

    xw_kernel<<<dim3((T + TM - 1) / TM, B), 256>>>(inputs, lengths, W, keys, T);
    dm_kernel<<<(B + 1) / 2, 512>>>(inputs, lengths, keys, U, V,
                                    gate_bias, state_bias, (float*)d_out, T, B);
}

// round 7
// speedup vs baseline: 1.4946x; 1.4946x over previous
#include <cuda_runtime.h>
#include <math.h>

#define DD 256   // feature dim D
#define SS 8     // memory slots S
#define MAXB 512
#define MAXT 256
#define TM 32    // rows per XW tile

typedef unsigned long long u64;

// ---- packed fp32x2 helpers (Blackwell; IEEE-identical to scalar fp32) ----
__device__ __forceinline__ u64 pack2(float lo, float hi) {
    u64 r; asm("mov.b64 %0, {%1, %2};" : "=l"(r) : "f"(lo), "f"(hi)); return r;
}
__device__ __forceinline__ void fma2(u64& acc, u64 a, u64 b) {
    asm("fma.rn.f32x2 %0, %1, %2, %0;" : "+l"(acc) : "l"(a), "l"(b));
}
__device__ __forceinline__ u64 add2(u64 a, u64 b) {
    u64 r; asm("add.rn.f32x2 %0, %1, %2;" : "=l"(r) : "l"(a), "l"(b)); return r;
}
__device__ __forceinline__ float2 unpack2(u64 v) {
    float lo, hi; asm("mov.b64 {%0, %1}, %2;" : "=f"(lo), "=f"(hi) : "l"(v));
    return make_float2(lo, hi);
}

// Legal scratch: __device__ globals.
__device__ float g_xw[(size_t)MAXB * MAXT * DD];         // x@W     [B,T,D]
__device__ float g_gk[(size_t)MAXB * MAXT * SS];         // x@keys^T[B,T,S]

// ---------------------------------------------------------------------------
// Precompute XW[b,t,:] = x@W and GK[b,t,:] = x@keys^T for t < len[b].
// ---------------------------------------------------------------------------
__global__ __launch_bounds__(256) void xw_kernel(
    const float* __restrict__ inputs,   // [B,T,D]
    const int*   __restrict__ lengths,
    const float* __restrict__ W,        // [D,D]
    const float* __restrict__ keys,     // [S,D]
    int T)
{
    const int b  = blockIdx.y;
    const int t0 = blockIdx.x * TM;
    if (t0 >= lengths[b]) return;        // fully-masked tile: no work
    const int rows = min(TM, T - t0);

    __shared__ __align__(16) float As[DD][TM];   // transposed x-tile, 32KB
    const float* A = inputs + ((size_t)b * T + t0) * DD;
    const int tid = threadIdx.x;

    for (int i = tid; i < rows * (DD / 4); i += 256) {
        const int m = i / (DD / 4), d4 = i % (DD / 4);
        const float4 v = *(const float4*)&A[(size_t)m * DD + d4 * 4];
        As[d4 * 4 + 0][m] = v.x;
        As[d4 * 4 + 1][m] = v.y;
        As[d4 * 4 + 2][m] = v.z;
        As[d4 * 4 + 3][m] = v.w;
    }
    __syncthreads();

    const int e = tid;
    u64 acc2[TM / 2];
#pragma unroll
    for (int m = 0; m < TM / 2; ++m) acc2[m] = 0ull;
    const float* wp = W + e;
#pragma unroll 2
    for (int d = 0; d < DD; ++d) {
        const float w = *wp; wp += DD;
        const u64 ww = pack2(w, w);
        const ulonglong2* ap = (const ulonglong2*)&As[d][0];
#pragma unroll
        for (int m4 = 0; m4 < TM / 4; ++m4) {
            const ulonglong2 a = ap[m4];
            fma2(acc2[m4 * 2 + 0], a.x, ww);
            fma2(acc2[m4 * 2 + 1], a.y, ww);
        }
    }
    float* o = g_xw + ((size_t)b * T + t0) * DD + e;
    for (int m = 0; m < rows; ++m) {
        const float2 f = unpack2(acc2[m >> 1]);
        o[(size_t)m * DD] = (m & 1) ? f.y : f.x;
    }

    // GK tail: 32 rows x 8 slots = 256 dot products, one per thread.
    {
        const int m = tid >> 3, s = tid & 7;
        if (m < rows) {
            const float* kp = keys + s * DD;
            float v = 0.f;
#pragma unroll 4
            for (int d = 0; d < DD; ++d) v = fmaf(As[d][m], kp[d], v);
            g_gk[((size_t)b * T + t0 + m) * SS + s] = v;
        }
    }
}

// ---------------------------------------------------------------------------
// Recurrence: one CTA of 256 threads per batch, len[b] steps.
// GEMM: 4-way d-split x 4 columns per thread. Thread (q = tid>>6, c = tid&63)
// accumulates all 8 slots for columns {c, c+64, c+128, c+192} over
// d in [64q, 64q+64) -- each broadcast st[d][*] LDS feeds 16 FMA2 (4 cols),
// each U element is loaded exactly once per CTA-step. Quarters exchange 32B
// partials per donated column via SMEM under S1; thread tid finalizes column
// e = tid (c + 64q == tid). Raw state + deferred per-slot norm scale r[] in
// registers; kvb in registers; 2 barriers per step; 128-reg budget.
// ---------------------------------------------------------------------------
__global__ __launch_bounds__(256, 2) void dm_kernel(
    const float* __restrict__ inputs,
    const int*   __restrict__ lengths,
    const float* __restrict__ keys,
    const float* __restrict__ U,
    const float* __restrict__ V,
    const float* __restrict__ gate_bias,
    const float* __restrict__ state_bias,
    float*       __restrict__ out,
    int T)
{
    const int b    = blockIdx.x;
    const int tid  = threadIdx.x;
    const int e    = tid;               // finalized column
    const int q    = tid >> 6;          // d-quarter
    const int c    = tid & 63;          // column base
    const int lane = tid & 31;
    const int warp = tid >> 5;

    __shared__ __align__(16) float st[DD][SS];     // raw h, transposed [d][s]
    __shared__ __align__(16) u64  buf[4][4][64][4];// [dest_q][src_q][c][pairs]
    __shared__ __align__(16) float red1[SS][8];    // gate partials [s][warp]
    __shared__ __align__(16) float red2[SS][8];    // norm partials [s][warp]

#pragma unroll
    for (int s = 0; s < SS; ++s)
        st[e][s] = keys[s * DD + e];    // init state = keys (raw, r=1)
    __syncthreads();

    // ---- kvb[e][s] = sum_d keys[s][d]*V[d][e] + sbias[e] (registers) ----
    float kv[SS];
    {
        u64 K01 = 0ull, K23 = 0ull, K45 = 0ull, K67 = 0ull;
        const float* vp = V + e;
#pragma unroll 8
        for (int d = 0; d < DD; ++d) {
            const float v = *vp; vp += DD;
            const u64 vv = pack2(v, v);
            const ulonglong2 r0 = *(const ulonglong2*)&st[d][0];  // == keys
            const ulonglong2 r1 = *(const ulonglong2*)&st[d][4];
            fma2(K01, r0.x, vv);
            fma2(K23, r0.y, vv);
            fma2(K45, r1.x, vv);
            fma2(K67, r1.y, vv);
        }
        const float sb = state_bias[e];
        const float2 k01 = unpack2(K01), k23 = unpack2(K23);
        const float2 k45 = unpack2(K45), k67 = unpack2(K67);
        kv[0] = k01.x + sb; kv[1] = k01.y + sb;
        kv[2] = k23.x + sb; kv[3] = k23.y + sb;
        kv[4] = k45.x + sb; kv[5] = k45.y + sb;
        kv[6] = k67.x + sb; kv[7] = k67.y + sb;
    }

    const int   len   = lengths[b];
    const float gbias = gate_bias[0];
    const float* xb  = inputs + (size_t)b * T * DD + e;
    const float* xwb = g_xw   + (size_t)b * T * DD + e;
    const float* gkb = g_gk   + (size_t)b * T * SS;
    const float* Up  = U + (size_t)(q * 64) * DD + c;

    float r[SS];
#pragma unroll
    for (int s = 0; s < SS; ++s) r[s] = 1.f;

    float xv = xb[0];                    // rotated: needed at phase-A start

    for (int t = 0; t < len; ++t) {
        // ---- phase A: gate partials (own column) + 4-col d-split GEMM ----
        const float4 s0 = *(const float4*)&st[e][0];
        const float4 s1 = *(const float4*)&st[e][4];
        float p[SS] = { xv * s0.x, xv * s0.y, xv * s0.z, xv * s0.w,
                        xv * s1.x, xv * s1.y, xv * s1.z, xv * s1.w };
#pragma unroll
        for (int s = 0; s < SS; ++s)
#pragma unroll
            for (int o = 16; o > 0; o >>= 1)
                p[s] += __shfl_xor_sync(0xffffffffu, p[s], o);
        if (lane == 0) {
#pragma unroll
            for (int s = 0; s < SS; ++s) red1[s][warp] = p[s];
        }

        // phase-B scalars for current t (GEMM hides the load latency),
        // plus next step's xv (needed at next phase-A start)
        const int tn = (t + 1 < len) ? t + 1 : len - 1;
        const float xv_n  = xb [(size_t)tn * DD];
        const float xwv   = xwb[(size_t)t * DD];
        const float4 gk0  = *(const float4*)&gkb[(size_t)t * SS];
        const float4 gk1  = *(const float4*)&gkb[(size_t)t * SS + 4];

        // GEMM: acc[j][k] = slot-pair k of column c+64j, own 64-row d-range
        u64 acc[4][4];
#pragma unroll
        for (int j = 0; j < 4; ++j)
#pragma unroll
            for (int k = 0; k < 4; ++k) acc[j][k] = 0ull;
        {
            const float* up = Up;
            const int d0 = q * 64;
#pragma unroll 4
            for (int dd = 0; dd < 64; ++dd) {
                const int d = d0 + dd;
                const float u0 = up[0], u1 = up[64], u2 = up[128], u3 = up[192];
                up += DD;
                const ulonglong2 r0 = *(const ulonglong2*)&st[d][0];
                const ulonglong2 r1 = *(const ulonglong2*)&st[d][4];
                const u64 uu0 = pack2(u0, u0);
                fma2(acc[0][0], r0.x, uu0); fma2(acc[0][1], r0.y, uu0);
                fma2(acc[0][2], r1.x, uu0); fma2(acc[0][3], r1.y, uu0);
                const u64 uu1 = pack2(u1, u1);
                fma2(acc[1][0], r0.x, uu1); fma2(acc[1][1], r0.y, uu1);
                fma2(acc[1][2], r1.x, uu1); fma2(acc[1][3], r1.y, uu1);
                const u64 uu2 = pack2(u2, u2);
                fma2(acc[2][0], r0.x, uu2); fma2(acc[2][1], r0.y, uu2);
                fma2(acc[2][2], r1.x, uu2); fma2(acc[2][3], r1.y, uu2);
                const u64 uu3 = pack2(u3, u3);
                fma2(acc[3][0], r0.x, uu3); fma2(acc[3][1], r0.y, uu3);
                fma2(acc[3][2], r1.x, uu3); fma2(acc[3][3], r1.y, uu3);
            }
        }
        // donate partials for the 3 columns other quarters finalize
#pragma unroll
        for (int j = 0; j < 4; ++j) {
            if (j != q) {
                ulonglong2 v0 = {acc[j][0], acc[j][1]};
                ulonglong2 v1 = {acc[j][2], acc[j][3]};
                *(ulonglong2*)&buf[j][q][c][0] = v0;
                *(ulonglong2*)&buf[j][q][c][2] = v1;
            }
        }
        __syncthreads();   // S1: red1 + buf visible; all st reads complete

        // ---- phase B: finalize own column e ----
        u64 P0 = acc[q][0], P1 = acc[q][1], P2 = acc[q][2], P3 = acc[q][3];
#pragma unroll
        for (int pq = 0; pq < 4; ++pq) {
            if (pq != q) {
                const ulonglong2 v0 = *(const ulonglong2*)&buf[q][pq][c][0];
                const ulonglong2 v1 = *(const ulonglong2*)&buf[q][pq][c][2];
                P0 = add2(P0, v0.x); P1 = add2(P1, v0.y);
                P2 = add2(P2, v1.x); P3 = add2(P3, v1.y);
            }
        }
        const float2 f0 = unpack2(P0), f1 = unpack2(P1);
        const float2 f2 = unpack2(P2), f3 = unpack2(P3);
        const float accf[SS] = {f0.x, f0.y, f1.x, f1.y, f2.x, f2.y, f3.x, f3.y};
        const float gk [SS] = {gk0.x, gk0.y, gk0.z, gk0.w,
                               gk1.x, gk1.y, gk1.z, gk1.w};
        const float sv [SS] = {s0.x, s0.y, s0.z, s0.w, s1.x, s1.y, s1.z, s1.w};
        float h[SS], qq[SS];
#pragma unroll
        for (int s = 0; s < SS; ++s) {
            const float4 u0 = *(const float4*)&red1[s][0];
            const float4 u1 = *(const float4*)&red1[s][4];
            const float ls = ((u0.x + u0.y) + (u0.z + u0.w))
                           + ((u1.x + u1.y) + (u1.z + u1.w));
            const float logit = fmaf(r[s], ls, gk[s] + gbias);
            const float g = __fdividef(1.f, 1.f + __expf(-logit));
            const float pre = fmaf(r[s], accf[s], kv[s] + xwv);
            const float ht  = pre > 0.f ? pre : (__expf(pre) - 1.f);
            h[s] = fmaf(r[s], sv[s], g * ht);
            qq[s] = h[s] * h[s];
        }
        *(float4*)&st[e][0] = make_float4(h[0], h[1], h[2], h[3]);
        *(float4*)&st[e][4] = make_float4(h[4], h[5], h[6], h[7]);
#pragma unroll
        for (int s = 0; s < SS; ++s)
#pragma unroll
            for (int o = 16; o > 0; o >>= 1)
                qq[s] += __shfl_xor_sync(0xffffffffu, qq[s], o);
        if (lane == 0) {
#pragma unroll
            for (int s = 0; s < SS; ++s) red2[s][warp] = qq[s];
        }
        __syncthreads();   // S2: red2 + st writes visible

#pragma unroll
        for (int s = 0; s < SS; ++s) {
            const float4 u0 = *(const float4*)&red2[s][0];
            const float4 u1 = *(const float4*)&red2[s][4];
            const float n2 = ((u0.x + u0.y) + (u0.z + u0.w))
                           + ((u1.x + u1.y) + (u1.z + u1.w));
            r[s] = (n2 > 1e-24f) ? rsqrtf(n2) : 1e12f;  // 1/max(||h||,1e-12)
        }
        xv = xv_n;
    }

    float* ob = out + (size_t)b * SS * DD + e;
#pragma unroll
    for (int s = 0; s < SS; ++s)
        ob[s * DD] = st[e][s] * r[s];
}

// ---------------------------------------------------------------------------
// Inputs: inputs, lengths, keys, U, V, W, gate_bias, state_bias. Out: [B,S,D].
// ---------------------------------------------------------------------------
extern "C" void kernel_launch(void* const* d_in, const int* in_sizes, int n_in,
                              void* d_out, int out_size) {
    const float* inputs     = (const float*)d_in[0];
    const int*   lengths    = (const int*)  d_in[1];
    const float* keys       = (const float*)d_in[2];
    const float* U          = (const float*)d_in[3];
    const float* V          = (const float*)d_in[4];
    const float* W          = (const float*)d_in[5];
    const float* gate_bias  = (const float*)d_in[6];
    const float* state_bias = (const float*)d_in[7];

    const int B = in_sizes[1];                 // lengths element count
    const int T = in_sizes[0] / (B * DD);      // inputs = B*T*D

    xw_kernel<<<dim3((T + TM - 1) / TM, B), 256>>>(inputs, lengths, W, keys, T);
    dm_kernel<<<B, DD>>>(inputs, lengths, keys, U, V, gate_bias, state_bias,
                         (float*)d_out, T);
}

// round 8
// speedup vs baseline: 1.7901x; 1.1977x over previous
#include <cuda_runtime.h>
#include <math.h>

#define DD 256   // feature dim D
#define SS 8     // memory slots S
#define MAXB 512
#define MAXT 256
#define TM 32    // rows per XW tile

typedef unsigned long long u64;

// ---- packed fp32x2 helpers (Blackwell; IEEE-identical to scalar fp32) ----
__device__ __forceinline__ u64 pack2(float lo, float hi) {
    u64 r; asm("mov.b64 %0, {%1, %2};" : "=l"(r) : "f"(lo), "f"(hi)); return r;
}
__device__ __forceinline__ void fma2(u64& acc, u64 a, u64 b) {
    asm("fma.rn.f32x2 %0, %1, %2, %0;" : "+l"(acc) : "l"(a), "l"(b));
}
__device__ __forceinline__ float2 unpack2(u64 v) {
    float lo, hi; asm("mov.b64 {%0, %1}, %2;" : "=f"(lo), "=f"(hi) : "l"(v));
    return make_float2(lo, hi);
}

// Legal scratch: __device__ globals.
__device__ float g_xw[(size_t)MAXB * MAXT * DD];         // x@W     [B,T,D]
__device__ float g_gk[(size_t)MAXB * MAXT * SS];         // x@keys^T[B,T,S]
__device__ int   g_perm[MAXB];                           // batches by desc len

// ---------------------------------------------------------------------------
// Counting sort: g_perm = batch indices in descending length order (LPT
// scheduling across the 2 CTA waves). Output is permutation-invariant.
// ---------------------------------------------------------------------------
__global__ void sort_kernel(const int* __restrict__ lengths, int B, int T) {
    __shared__ int cnt[MAXT + 1];
    __shared__ int off[MAXT + 1];
    const int tid = threadIdx.x;
    for (int i = tid; i <= T; i += blockDim.x) cnt[i] = 0;
    __syncthreads();
    for (int b = tid; b < B; b += blockDim.x) atomicAdd(&cnt[lengths[b]], 1);
    __syncthreads();
    if (tid == 0) {
        int acc = 0;
        for (int l = T; l >= 1; --l) { off[l] = acc; acc += cnt[l]; }
    }
    __syncthreads();
    for (int b = tid; b < B; b += blockDim.x) {
        const int pos = atomicAdd(&off[lengths[b]], 1);
        g_perm[pos] = b;
    }
}

// ---------------------------------------------------------------------------
// Precompute XW[b,t,:] = x@W and GK[b,t,:] = x@keys^T for t < len[b].
// ---------------------------------------------------------------------------
__global__ __launch_bounds__(256) void xw_kernel(
    const float* __restrict__ inputs,   // [B,T,D]
    const int*   __restrict__ lengths,
    const float* __restrict__ W,        // [D,D]
    const float* __restrict__ keys,     // [S,D]
    int T)
{
    const int b  = blockIdx.y;
    const int t0 = blockIdx.x * TM;
    if (t0 >= lengths[b]) return;        // fully-masked tile: no work
    const int rows = min(TM, T - t0);

    __shared__ __align__(16) float As[DD][TM];   // transposed x-tile, 32KB
    const float* A = inputs + ((size_t)b * T + t0) * DD;
    const int tid = threadIdx.x;

    for (int i = tid; i < rows * (DD / 4); i += 256) {
        const int m = i / (DD / 4), d4 = i % (DD / 4);
        const float4 v = *(const float4*)&A[(size_t)m * DD + d4 * 4];
        As[d4 * 4 + 0][m] = v.x;
        As[d4 * 4 + 1][m] = v.y;
        As[d4 * 4 + 2][m] = v.z;
        As[d4 * 4 + 3][m] = v.w;
    }
    __syncthreads();

    const int e = tid;
    u64 acc2[TM / 2];
#pragma unroll
    for (int m = 0; m < TM / 2; ++m) acc2[m] = 0ull;
    const float* wp = W + e;
#pragma unroll 2
    for (int d = 0; d < DD; ++d) {
        const float w = *wp; wp += DD;
        const u64 ww = pack2(w, w);
        const ulonglong2* ap = (const ulonglong2*)&As[d][0];
#pragma unroll
        for (int m4 = 0; m4 < TM / 4; ++m4) {
            const ulonglong2 a = ap[m4];
            fma2(acc2[m4 * 2 + 0], a.x, ww);
            fma2(acc2[m4 * 2 + 1], a.y, ww);
        }
    }
    float* o = g_xw + ((size_t)b * T + t0) * DD + e;
    for (int m = 0; m < rows; ++m) {
        const float2 f = unpack2(acc2[m >> 1]);
        o[(size_t)m * DD] = (m & 1) ? f.y : f.x;
    }

    // GK tail: 32 rows x 8 slots = 256 dot products, one per thread.
    {
        const int m = tid >> 3, s = tid & 7;
        if (m < rows) {
            const float* kp = keys + s * DD;
            float v = 0.f;
#pragma unroll 4
            for (int d = 0; d < DD; ++d) v = fmaf(As[d][m], kp[d], v);
            g_gk[((size_t)b * T + t0 + m) * SS + s] = v;
        }
    }
}

// ---------------------------------------------------------------------------
// Recurrence: one CTA of 256 threads per batch (perm order), len[b] steps.
// State stored DUPLICATED in SMEM: stdup[d][s] = (h,h) as u64, so the GEMM's
// a-operand needs no pack. b-operand = LDG.64 of two ADJACENT U columns
// (natural float2). Thread (q = tid>>6, c = tid&63) computes cols
// {2c, 2c+1, 2c+128, 2c+129} over d in [64q, 64q+64): per iter
// 2 LDG.64 + 4 LDS.128 + 16 FMA2 (no packs). Thread finalizes col
// e = [2c, 2c+1, 2c+128, 2c+129][q] (bijection over 256 cols); the other
// 3 computed cols are donated via SMEM under S1. Raw state + deferred
// per-slot norm scale r[]; kvb in registers; 2 barriers/step.
// ---------------------------------------------------------------------------
__global__ __launch_bounds__(256, 2) void dm_kernel(
    const float* __restrict__ inputs,
    const int*   __restrict__ lengths,
    const float* __restrict__ keys,
    const float* __restrict__ U,
    const float* __restrict__ V,
    const float* __restrict__ gate_bias,
    const float* __restrict__ state_bias,
    float*       __restrict__ out,
    int T)
{
    const int b    = g_perm[blockIdx.x];
    const int tid  = threadIdx.x;
    const int q    = tid >> 6;          // d-quarter
    const int c    = tid & 63;          // column-pair base
    const int e    = 2 * c + (q & 1) + (q >> 1) * 128;  // finalized column
    const int lane = tid & 31;
    const int warp = tid >> 5;

    // stdup row padded to 10 u64 (80B) -> 16B-aligned rows, mild banking
    __shared__ __align__(16) u64   stdup[DD][SS + 2];   // dup raw h  (20KB)
    __shared__ __align__(16) float buf[3][DD][SS];      // donations  (24KB)
    __shared__ __align__(16) float red1[SS][8];         // gate partials
    __shared__ __align__(16) float red2[SS][8];         // norm partials

#pragma unroll
    for (int s = 0; s < SS; ++s) {
        const float k = keys[s * DD + e];
        stdup[e][s] = pack2(k, k);      // init state = keys (raw, r=1)
    }
    __syncthreads();

    // ---- kvb[e][s] = sum_d keys[s][d]*V[d][e] + sbias[e] (registers) ----
    float kv[SS];
    {
        float a[SS];
#pragma unroll
        for (int s = 0; s < SS; ++s) a[s] = 0.f;
        const float* vp = V + e;
#pragma unroll 4
        for (int d = 0; d < DD; ++d) {
            const float v = *vp; vp += DD;
            const ulonglong2 p01 = *(const ulonglong2*)&stdup[d][0];
            const ulonglong2 p23 = *(const ulonglong2*)&stdup[d][2];
            const ulonglong2 p45 = *(const ulonglong2*)&stdup[d][4];
            const ulonglong2 p67 = *(const ulonglong2*)&stdup[d][6];
            a[0] = fmaf(unpack2(p01.x).x, v, a[0]);
            a[1] = fmaf(unpack2(p01.y).x, v, a[1]);
            a[2] = fmaf(unpack2(p23.x).x, v, a[2]);
            a[3] = fmaf(unpack2(p23.y).x, v, a[3]);
            a[4] = fmaf(unpack2(p45.x).x, v, a[4]);
            a[5] = fmaf(unpack2(p45.y).x, v, a[5]);
            a[6] = fmaf(unpack2(p67.x).x, v, a[6]);
            a[7] = fmaf(unpack2(p67.y).x, v, a[7]);
        }
        const float sb = state_bias[e];
#pragma unroll
        for (int s = 0; s < SS; ++s) kv[s] = a[s] + sb;
    }

    const int   len   = lengths[b];
    const float gbias = gate_bias[0];
    const float* xb  = inputs + (size_t)b * T * DD + e;
    const float* xwb = g_xw   + (size_t)b * T * DD + e;
    const float* gkb = g_gk   + (size_t)b * T * SS;
    const float* UA  = U + (size_t)(q * 64) * DD + 2 * c;        // cols 2c,2c+1
    const float* UB  = UA + 128;                                 // +128,+129

    float r[SS];
#pragma unroll
    for (int s = 0; s < SS; ++s) r[s] = 1.f;

    float xv = xb[0];                    // needed at phase-A start

    for (int t = 0; t < len; ++t) {
        // ---- phase A: gate partials (own column e) ----
        const ulonglong2 m01 = *(const ulonglong2*)&stdup[e][0];
        const ulonglong2 m23 = *(const ulonglong2*)&stdup[e][2];
        const ulonglong2 m45 = *(const ulonglong2*)&stdup[e][4];
        const ulonglong2 m67 = *(const ulonglong2*)&stdup[e][6];
        const float sv[SS] = {
            unpack2(m01.x).x, unpack2(m01.y).x, unpack2(m23.x).x,
            unpack2(m23.y).x, unpack2(m45.x).x, unpack2(m45.y).x,
            unpack2(m67.x).x, unpack2(m67.y).x };
        float p[SS];
#pragma unroll
        for (int s = 0; s < SS; ++s) p[s] = xv * sv[s];
#pragma unroll
        for (int s = 0; s < SS; ++s)
#pragma unroll
            for (int o = 16; o > 0; o >>= 1)
                p[s] += __shfl_xor_sync(0xffffffffu, p[s], o);
        if (lane == 0) {
#pragma unroll
            for (int s = 0; s < SS; ++s) red1[s][warp] = p[s];
        }

        // phase-B scalars for current t + next step's xv (GEMM hides latency)
        const int tn = (t + 1 < len) ? t + 1 : len - 1;
        const float xv_n  = xb [(size_t)tn * DD];
        const float xwv   = xwb[(size_t)t * DD];
        const float4 gk0  = *(const float4*)&gkb[(size_t)t * SS];
        const float4 gk1  = *(const float4*)&gkb[(size_t)t * SS + 4];

        // ---- GEMM: accA[s] = (col 2c, col 2c+1), accB[s] = (+128, +129) ----
        u64 accA[SS], accB[SS];
#pragma unroll
        for (int s = 0; s < SS; ++s) { accA[s] = 0ull; accB[s] = 0ull; }
        {
            const float* ua = UA;
            const float* ub = UB;
            const int d0 = q * 64;
#pragma unroll 4
            for (int dd = 0; dd < 64; ++dd) {
                const int d = d0 + dd;
                const u64 uA = *(const u64*)ua;  ua += DD;
                const u64 uB = *(const u64*)ub;  ub += DD;
                const ulonglong2 s01 = *(const ulonglong2*)&stdup[d][0];
                const ulonglong2 s23 = *(const ulonglong2*)&stdup[d][2];
                const ulonglong2 s45 = *(const ulonglong2*)&stdup[d][4];
                const ulonglong2 s67 = *(const ulonglong2*)&stdup[d][6];
                fma2(accA[0], s01.x, uA); fma2(accB[0], s01.x, uB);
                fma2(accA[1], s01.y, uA); fma2(accB[1], s01.y, uB);
                fma2(accA[2], s23.x, uA); fma2(accB[2], s23.x, uB);
                fma2(accA[3], s23.y, uA); fma2(accB[3], s23.y, uB);
                fma2(accA[4], s45.x, uA); fma2(accB[4], s45.x, uB);
                fma2(accA[5], s45.y, uA); fma2(accB[5], s45.y, uB);
                fma2(accA[6], s67.x, uA); fma2(accB[6], s67.x, uB);
                fma2(accA[7], s67.y, uA); fma2(accB[7], s67.y, uB);
            }
        }
        // unpack: per-column values for the 4 computed columns
        float vA0[SS], vA1[SS], vB0[SS], vB1[SS];
#pragma unroll
        for (int s = 0; s < SS; ++s) {
            const float2 fa = unpack2(accA[s]);
            const float2 fb = unpack2(accB[s]);
            vA0[s] = fa.x; vA1[s] = fa.y; vB0[s] = fb.x; vB1[s] = fb.y;
        }
        // donate 3 non-finalized columns: slot(k,q) = q - (q > k)
#pragma unroll
        for (int k = 0; k < 4; ++k) {
            if (k != q) {
                const int X  = 2 * c + (k & 1) + (k >> 1) * 128;
                const int ds = q - (q > k ? 1 : 0);
                const float* v = (k == 0) ? vA0 : (k == 1) ? vA1
                               : (k == 2) ? vB0 : vB1;
                *(float4*)&buf[ds][X][0] = make_float4(v[0], v[1], v[2], v[3]);
                *(float4*)&buf[ds][X][4] = make_float4(v[4], v[5], v[6], v[7]);
            }
        }
        __syncthreads();   // S1: red1 + buf visible; all stdup reads complete

        // ---- phase B: finalize own column e ----
        float accf[SS];
        {
            const float* own = (q == 0) ? vA0 : (q == 1) ? vA1
                             : (q == 2) ? vB0 : vB1;
#pragma unroll
            for (int s = 0; s < SS; ++s) accf[s] = own[s];
#pragma unroll
            for (int j = 0; j < 3; ++j) {
                const float4 r0 = *(const float4*)&buf[j][e][0];
                const float4 r1 = *(const float4*)&buf[j][e][4];
                accf[0] += r0.x; accf[1] += r0.y;
                accf[2] += r0.z; accf[3] += r0.w;
                accf[4] += r1.x; accf[5] += r1.y;
                accf[6] += r1.z; accf[7] += r1.w;
            }
        }
        const float gk[SS] = {gk0.x, gk0.y, gk0.z, gk0.w,
                              gk1.x, gk1.y, gk1.z, gk1.w};
        float h[SS], qq[SS];
#pragma unroll
        for (int s = 0; s < SS; ++s) {
            const float4 u0 = *(const float4*)&red1[s][0];
            const float4 u1 = *(const float4*)&red1[s][4];
            const float ls = ((u0.x + u0.y) + (u0.z + u0.w))
                           + ((u1.x + u1.y) + (u1.z + u1.w));
            const float logit = fmaf(r[s], ls, gk[s] + gbias);
            const float g = __fdividef(1.f, 1.f + __expf(-logit));
            const float pre = fmaf(r[s], accf[s], kv[s] + xwv);
            const float ht  = pre > 0.f ? pre : (__expf(pre) - 1.f);
            h[s] = fmaf(r[s], sv[s], g * ht);
            qq[s] = h[s] * h[s];
        }
        {
            ulonglong2 w01 = {pack2(h[0], h[0]), pack2(h[1], h[1])};
            ulonglong2 w23 = {pack2(h[2], h[2]), pack2(h[3], h[3])};
            ulonglong2 w45 = {pack2(h[4], h[4]), pack2(h[5], h[5])};
            ulonglong2 w67 = {pack2(h[6], h[6]), pack2(h[7], h[7])};
            *(ulonglong2*)&stdup[e][0] = w01;
            *(ulonglong2*)&stdup[e][2] = w23;
            *(ulonglong2*)&stdup[e][4] = w45;
            *(ulonglong2*)&stdup[e][6] = w67;
        }
#pragma unroll
        for (int s = 0; s < SS; ++s)
#pragma unroll
            for (int o = 16; o > 0; o >>= 1)
                qq[s] += __shfl_xor_sync(0xffffffffu, qq[s], o);
        if (lane == 0) {
#pragma unroll
            for (int s = 0; s < SS; ++s) red2[s][warp] = qq[s];
        }
        __syncthreads();   // S2: red2 + stdup writes visible

#pragma unroll
        for (int s = 0; s < SS; ++s) {
            const float4 u0 = *(const float4*)&red2[s][0];
            const float4 u1 = *(const float4*)&red2[s][4];
            const float n2 = ((u0.x + u0.y) + (u0.z + u0.w))
                           + ((u1.x + u1.y) + (u1.z + u1.w));
            r[s] = (n2 > 1e-24f) ? rsqrtf(n2) : 1e12f;  // 1/max(||h||,1e-12)
        }
        xv = xv_n;
    }

    float* ob = out + (size_t)b * SS * DD + e;
#pragma unroll
    for (int s = 0; s < SS; ++s)
        ob[s * DD] = unpack2(stdup[e][s]).x * r[s];
}

// ---------------------------------------------------------------------------
// Inputs: inputs, lengths, keys, U, V, W, gate_bias, state_bias. Out: [B,S,D].
// ---------------------------------------------------------------------------
extern "C" void kernel_launch(void* const* d_in, const int* in_sizes, int n_in,
                              void* d_out, int out_size) {
    const float* inputs     = (const float*)d_in[0];
    const int*   lengths    = (const int*)  d_in[1];
    const float* keys       = (const float*)d_in[2];
    const float* U          = (const float*)d_in[3];
    const float* V          = (const float*)d_in[4];
    const float* W          = (const float*)d_in[5];
    const float* gate_bias  = (const float*)d_in[6];
    const float* state_bias = (const float*)d_in[7];

    const int B = in_sizes[1];                 // lengths element count
    const int T = in_sizes[0] / (B * DD);      // inputs = B*T*D

    sort_kernel<<<1, 256>>>(lengths, B, T);
    xw_kernel<<<dim3((T + TM - 1) / TM, B), 256>>>(inputs, lengths, W, keys, T);
    dm_kernel<<<B, DD>>>(inputs, lengths, keys, U, V, gate_bias, state_bias,
                         (float*)d_out, T);
}